// round 1
// baseline (speedup 1.0000x reference)
#include <cuda_runtime.h>

#define N_NODES 50000
#define N_PAD   50048      // 782 * 64, pads GEMM row tiles
#define N_EDGES 800000
#define D_FEAT  128
#define UNITS   256

// Scratch (zero-initialized at module load; pad rows are never written)
__device__ float g_deg[N_PAD];
__device__ float g_norm[(size_t)N_PAD * D_FEAT];
__device__ float g_pooled[(size_t)N_PAD * D_FEAT];

// ---------------------------------------------------------------- degree ----
__global__ void zero_deg_kernel() {
    int i = blockIdx.x * blockDim.x + threadIdx.x;
    if (i < N_NODES) g_deg[i] = 0.0f;
}

__global__ void degree_kernel(const int* __restrict__ erow,
                              const float* __restrict__ eval) {
    int e = blockIdx.x * blockDim.x + threadIdx.x;
    if (e < N_EDGES) atomicAdd(&g_deg[erow[e]], eval[e]);
}

// ------------------------------------------- normalize + self-loop init ----
// normalized[n]  = rsqrt(deg[n]+1) * features[n]
// pooled_init[n] = rsqrt(deg[n]+1) * normalized[n]
__global__ void normalize_kernel(const float* __restrict__ feat) {
    int idx = blockIdx.x * blockDim.x + threadIdx.x;   // float4 index
    const int total = N_NODES * (D_FEAT / 4);
    if (idx >= total) return;
    int n = idx >> 5;                                  // /(D_FEAT/4)
    float inv = rsqrtf(g_deg[n] + 1.0f);
    float4 f = __ldg(((const float4*)feat) + idx);
    float4 nm = make_float4(f.x * inv, f.y * inv, f.z * inv, f.w * inv);
    ((float4*)g_norm)[idx] = nm;
    float4 p = make_float4(nm.x * inv, nm.y * inv, nm.z * inv, nm.w * inv);
    ((float4*)g_pooled)[idx] = p;
}

// ---------------------------------------------------------- scatter SpMM ----
// One warp per edge; each lane handles 4 contiguous floats via red.global.v4.f32
__global__ void scatter_kernel(const int* __restrict__ erow,
                               const int* __restrict__ ecol,
                               const float* __restrict__ eval) {
    int gid  = blockIdx.x * blockDim.x + threadIdx.x;
    int e    = gid >> 5;
    int lane = threadIdx.x & 31;
    if (e >= N_EDGES) return;
    int   r = erow[e];
    int   c = ecol[e];
    float v = eval[e];
    float4 m = __ldg(((const float4*)(g_norm + (size_t)c * D_FEAT)) + lane);
    float* dst = g_pooled + (size_t)r * D_FEAT + lane * 4;
    asm volatile("red.global.add.v4.f32 [%0], {%1, %2, %3, %4};"
                 :: "l"(dst), "f"(v * m.x), "f"(v * m.y),
                    "f"(v * m.z), "f"(v * m.w)
                 : "memory");
}

// ----------------------------------------------------------- GEMM + ReLU ----
// out[N,256] = relu(pooled[N,128] @ W[128,256])
// BM=64, BN=64, BK=32, 256 threads, 4x4 micro-tile per thread.
__global__ void __launch_bounds__(256)
gemm_relu_kernel(const float* __restrict__ W, float* __restrict__ out) {
    __shared__ float As[64][33];   // pad 33: conflict-free scalar access
    __shared__ float Bs[32][64];

    const int tx = threadIdx.x & 15;        // 0..15 -> N
    const int ty = threadIdx.x >> 4;        // 0..15 -> M
    const int bm = blockIdx.x * 64;
    const int bn = blockIdx.y * 64;

    float acc[4][4] = {};

    for (int bk = 0; bk < D_FEAT; bk += 32) {
        // A tile: pooled[(bm+r)*128 + bk + k], coalesced float4 loads
        #pragma unroll
        for (int t = threadIdx.x; t < 512; t += 256) {
            int r  = t >> 3;          // 0..63
            int k4 = t & 7;           // 0..7
            float4 a = *(const float4*)&g_pooled[(size_t)(bm + r) * D_FEAT + bk + k4 * 4];
            As[r][k4 * 4 + 0] = a.x;
            As[r][k4 * 4 + 1] = a.y;
            As[r][k4 * 4 + 2] = a.z;
            As[r][k4 * 4 + 3] = a.w;
        }
        // B tile: W[(bk+k)*256 + bn + n], coalesced float4 loads
        #pragma unroll
        for (int t = threadIdx.x; t < 512; t += 256) {
            int k  = t >> 4;          // 0..31
            int n4 = t & 15;          // 0..15
            *(float4*)&Bs[k][n4 * 4] =
                *(const float4*)&W[(size_t)(bk + k) * UNITS + bn + n4 * 4];
        }
        __syncthreads();

        #pragma unroll
        for (int k = 0; k < 32; k++) {
            float a0 = As[ty * 4 + 0][k];
            float a1 = As[ty * 4 + 1][k];
            float a2 = As[ty * 4 + 2][k];
            float a3 = As[ty * 4 + 3][k];
            float4 b = *(float4*)&Bs[k][tx * 4];
            acc[0][0] += a0 * b.x; acc[0][1] += a0 * b.y; acc[0][2] += a0 * b.z; acc[0][3] += a0 * b.w;
            acc[1][0] += a1 * b.x; acc[1][1] += a1 * b.y; acc[1][2] += a1 * b.z; acc[1][3] += a1 * b.w;
            acc[2][0] += a2 * b.x; acc[2][1] += a2 * b.y; acc[2][2] += a2 * b.z; acc[2][3] += a2 * b.w;
            acc[3][0] += a3 * b.x; acc[3][1] += a3 * b.y; acc[3][2] += a3 * b.z; acc[3][3] += a3 * b.w;
        }
        __syncthreads();
    }

    #pragma unroll
    for (int i = 0; i < 4; i++) {
        int row = bm + ty * 4 + i;
        if (row < N_NODES) {
            float4 o;
            o.x = fmaxf(acc[i][0], 0.0f);
            o.y = fmaxf(acc[i][1], 0.0f);
            o.z = fmaxf(acc[i][2], 0.0f);
            o.w = fmaxf(acc[i][3], 0.0f);
            *(float4*)&out[(size_t)row * UNITS + bn + tx * 4] = o;
        }
    }
}

// ------------------------------------------------------------------ launch --
extern "C" void kernel_launch(void* const* d_in, const int* in_sizes, int n_in,
                              void* d_out, int out_size) {
    const float* features = (const float*)d_in[0];
    const int*   edge_row = (const int*)d_in[1];
    const int*   edge_col = (const int*)d_in[2];
    const float* edge_val = (const float*)d_in[3];
    const float* W        = (const float*)d_in[4];
    float*       out      = (float*)d_out;

    zero_deg_kernel<<<(N_NODES + 255) / 256, 256>>>();
    degree_kernel<<<(N_EDGES + 255) / 256, 256>>>(edge_row, edge_val);

    const int nf4 = N_NODES * (D_FEAT / 4);
    normalize_kernel<<<(nf4 + 255) / 256, 256>>>(features);

    // one warp per edge: 800000 warps, 8 edges per 256-thread block
    scatter_kernel<<<(N_EDGES * 32 + 255) / 256, 256>>>(edge_row, edge_col, edge_val);

    dim3 grid(N_PAD / 64, UNITS / 64);
    gemm_relu_kernel<<<grid, 256>>>(W, out);
}

// round 3
// speedup vs baseline: 1.1747x; 1.1747x over previous
#include <cuda_runtime.h>
#include <cuda_bf16.h>
#include <cstdint>

#define N_NODES 50000
#define N_PAD   50048      // 391 * 128
#define N_EDGES 800000
#define D_FEAT  128
#define UNITS   256

// ---------------------------------------------------------------- scratch ---
__device__ float g_deg[N_PAD];
__device__ float g_norm[(size_t)N_PAD * D_FEAT];
__device__ float g_pooled[(size_t)N_PAD * D_FEAT];
// bf16 split operands (zero-init; pad rows never written -> stay zero)
__device__ __nv_bfloat16 g_Ahi[(size_t)N_PAD * D_FEAT];
__device__ __nv_bfloat16 g_Alo[(size_t)N_PAD * D_FEAT];
__device__ __nv_bfloat16 g_Whi[(size_t)UNITS * D_FEAT];   // transposed: [n][k]
__device__ __nv_bfloat16 g_Wlo[(size_t)UNITS * D_FEAT];

// ---------------------------------------------------------------- degree ----
__global__ void zero_deg_kernel() {
    int i = blockIdx.x * blockDim.x + threadIdx.x;
    if (i < N_NODES) g_deg[i] = 0.0f;
}

__global__ void degree_kernel(const int* __restrict__ erow,
                              const float* __restrict__ eval) {
    int e = blockIdx.x * blockDim.x + threadIdx.x;
    if (e < N_EDGES) atomicAdd(&g_deg[erow[e]], eval[e]);
}

// ------------------------------------------- normalize + self-loop init ----
__global__ void normalize_kernel(const float* __restrict__ feat) {
    int idx = blockIdx.x * blockDim.x + threadIdx.x;   // float4 index
    const int total = N_NODES * (D_FEAT / 4);
    if (idx >= total) return;
    int n = idx >> 5;
    float inv = rsqrtf(g_deg[n] + 1.0f);
    float4 f = __ldg(((const float4*)feat) + idx);
    float4 nm = make_float4(f.x * inv, f.y * inv, f.z * inv, f.w * inv);
    ((float4*)g_norm)[idx] = nm;
    float4 p = make_float4(nm.x * inv, nm.y * inv, nm.z * inv, nm.w * inv);
    ((float4*)g_pooled)[idx] = p;
}

// ---------------------------------------------------------- scatter SpMM ----
__global__ void scatter_kernel(const int* __restrict__ erow,
                               const int* __restrict__ ecol,
                               const float* __restrict__ eval) {
    int gid  = blockIdx.x * blockDim.x + threadIdx.x;
    int e    = gid >> 5;
    int lane = threadIdx.x & 31;
    if (e >= N_EDGES) return;
    int   r = erow[e];
    int   c = ecol[e];
    float v = eval[e];
    float4 m = __ldg(((const float4*)(g_norm + (size_t)c * D_FEAT)) + lane);
    float* dst = g_pooled + (size_t)r * D_FEAT + lane * 4;
    asm volatile("red.global.add.v4.f32 [%0], {%1, %2, %3, %4};"
                 :: "l"(dst), "f"(v * m.x), "f"(v * m.y),
                    "f"(v * m.z), "f"(v * m.w)
                 : "memory");
}

// ------------------------------------------------------------ bf16 split ----
__device__ __forceinline__ void bf16_split(float x, __nv_bfloat16& hi,
                                           __nv_bfloat16& lo) {
    hi = __float2bfloat16(x);
    lo = __float2bfloat16(x - __bfloat162float(hi));
}

__global__ void split_A_kernel() {
    int idx = blockIdx.x * blockDim.x + threadIdx.x;    // float4 index
    const int total = N_PAD * (D_FEAT / 4);
    if (idx >= total) return;
    float4 x = ((const float4*)g_pooled)[idx];
    __nv_bfloat16 h0, h1, h2, h3, l0, l1, l2, l3;
    bf16_split(x.x, h0, l0);
    bf16_split(x.y, h1, l1);
    bf16_split(x.z, h2, l2);
    bf16_split(x.w, h3, l3);
    ((__nv_bfloat162*)g_Ahi)[idx * 2 + 0] = __nv_bfloat162(h0, h1);
    ((__nv_bfloat162*)g_Ahi)[idx * 2 + 1] = __nv_bfloat162(h2, h3);
    ((__nv_bfloat162*)g_Alo)[idx * 2 + 0] = __nv_bfloat162(l0, l1);
    ((__nv_bfloat162*)g_Alo)[idx * 2 + 1] = __nv_bfloat162(l2, l3);
}

__global__ void split_W_kernel(const float* __restrict__ W) {
    int k = blockIdx.x;        // 0..127
    int n = threadIdx.x;       // 0..255
    float x = W[(size_t)k * UNITS + n];
    __nv_bfloat16 hi, lo;
    bf16_split(x, hi, lo);
    g_Whi[(size_t)n * D_FEAT + k] = hi;    // transposed [n][k]
    g_Wlo[(size_t)n * D_FEAT + k] = lo;
}

// ----------------------------------------------- mma.sync bf16x3 GEMM -------
// out[N,256] = relu( A(128x128 fp32) @ W ) via
//   A_hi@W_hi + A_lo@W_hi + A_hi@W_lo   (each bf16, fp32 accum)
// CTA tile 128x128, 8 warps (4m x 2n), warp tile 32x64, m16n8k16 mma.

#define AS_STRIDE 136   // bf16 elems per smem row (128 + 8 pad): bank stride 4

__global__ void __launch_bounds__(256)
gemm_mma_kernel(float* __restrict__ out) {
    extern __shared__ __nv_bfloat16 smem[];
    __nv_bfloat16* As = smem;                        // [128][AS_STRIDE]
    __nv_bfloat16* Bs = smem + 128 * AS_STRIDE;      // [128][AS_STRIDE], [n][k]

    const int tid  = threadIdx.x;
    const int wid  = tid >> 5;
    const int lane = tid & 31;
    const int g    = lane >> 2;       // group id (0..7)
    const int tg   = lane & 3;        // thread in group
    const int wm   = (wid & 3) * 32;  // warp m offset in CTA tile
    const int wn   = (wid >> 2) * 64; // warp n offset in CTA tile
    const int bm   = blockIdx.x * 128;
    const int bn   = blockIdx.y * 128;

    float acc[2][8][4];
    #pragma unroll
    for (int i = 0; i < 2; i++)
        #pragma unroll
        for (int j = 0; j < 8; j++)
            #pragma unroll
            for (int q = 0; q < 4; q++) acc[i][j][q] = 0.0f;

    const __nv_bfloat16* Asrc[3] = { g_Ahi, g_Alo, g_Ahi };
    const __nv_bfloat16* Bsrc[3] = { g_Whi, g_Whi, g_Wlo };

    for (int p = 0; p < 3; p++) {
        // A tile: rows bm..bm+127, full K=128 -> contiguous 2048 uint4 block
        const uint4* Ag = (const uint4*)(Asrc[p] + (size_t)bm * D_FEAT);
        const uint4* Bg = (const uint4*)(Bsrc[p] + (size_t)bn * D_FEAT);
        #pragma unroll
        for (int i = tid; i < 2048; i += 256) {
            int r = i >> 4, c = i & 15;
            *(uint4*)(As + r * AS_STRIDE + c * 8) = __ldg(Ag + i);
        }
        #pragma unroll
        for (int i = tid; i < 2048; i += 256) {
            int r = i >> 4, c = i & 15;
            *(uint4*)(Bs + r * AS_STRIDE + c * 8) = __ldg(Bg + i);
        }
        __syncthreads();

        #pragma unroll
        for (int kk = 0; kk < D_FEAT; kk += 16) {
            uint32_t a[2][4];
            #pragma unroll
            for (int i = 0; i < 2; i++) {
                const __nv_bfloat16* base =
                    As + (wm + i * 16 + g) * AS_STRIDE + kk + tg * 2;
                a[i][0] = *(const uint32_t*)(base);
                a[i][1] = *(const uint32_t*)(base + 8 * AS_STRIDE);
                a[i][2] = *(const uint32_t*)(base + 8);
                a[i][3] = *(const uint32_t*)(base + 8 * AS_STRIDE + 8);
            }
            uint32_t b[8][2];
            #pragma unroll
            for (int j = 0; j < 8; j++) {
                const __nv_bfloat16* base =
                    Bs + (wn + j * 8 + g) * AS_STRIDE + kk + tg * 2;
                b[j][0] = *(const uint32_t*)(base);
                b[j][1] = *(const uint32_t*)(base + 8);
            }
            #pragma unroll
            for (int i = 0; i < 2; i++)
                #pragma unroll
                for (int j = 0; j < 8; j++) {
                    asm volatile(
                        "mma.sync.aligned.m16n8k16.row.col.f32.bf16.bf16.f32 "
                        "{%0,%1,%2,%3}, {%4,%5,%6,%7}, {%8,%9}, {%0,%1,%2,%3};"
                        : "+f"(acc[i][j][0]), "+f"(acc[i][j][1]),
                          "+f"(acc[i][j][2]), "+f"(acc[i][j][3])
                        : "r"(a[i][0]), "r"(a[i][1]), "r"(a[i][2]), "r"(a[i][3]),
                          "r"(b[j][0]), "r"(b[j][1]));
                }
        }
        __syncthreads();
    }

    // epilogue: relu + store (float2 per fragment half-row)
    #pragma unroll
    for (int i = 0; i < 2; i++) {
        int row0 = bm + wm + i * 16 + g;
        int row1 = row0 + 8;
        #pragma unroll
        for (int j = 0; j < 8; j++) {
            int col = bn + wn + j * 8 + tg * 2;
            if (row0 < N_NODES) {
                float2 o0 = make_float2(fmaxf(acc[i][j][0], 0.0f),
                                        fmaxf(acc[i][j][1], 0.0f));
                *(float2*)&out[(size_t)row0 * UNITS + col] = o0;
            }
            if (row1 < N_NODES) {
                float2 o1 = make_float2(fmaxf(acc[i][j][2], 0.0f),
                                        fmaxf(acc[i][j][3], 0.0f));
                *(float2*)&out[(size_t)row1 * UNITS + col] = o1;
            }
        }
    }
}

#define GEMM_SMEM_BYTES (2 * 128 * AS_STRIDE * 2)   // 69632

// ------------------------------------------------------------------ launch --
extern "C" void kernel_launch(void* const* d_in, const int* in_sizes, int n_in,
                              void* d_out, int out_size) {
    const float* features = (const float*)d_in[0];
    const int*   edge_row = (const int*)d_in[1];
    const int*   edge_col = (const int*)d_in[2];
    const float* edge_val = (const float*)d_in[3];
    const float* W        = (const float*)d_in[4];
    float*       out      = (float*)d_out;

    zero_deg_kernel<<<(N_NODES + 255) / 256, 256>>>();
    degree_kernel<<<(N_EDGES + 255) / 256, 256>>>(edge_row, edge_val);

    const int nf4 = N_NODES * (D_FEAT / 4);
    normalize_kernel<<<(nf4 + 255) / 256, 256>>>(features);

    scatter_kernel<<<(N_EDGES * 32 + 255) / 256, 256>>>(edge_row, edge_col, edge_val);

    const int na4 = N_PAD * (D_FEAT / 4);
    split_A_kernel<<<(na4 + 255) / 256, 256>>>();
    split_W_kernel<<<D_FEAT, UNITS>>>(W);

    static bool smem_set = false;
    if (!smem_set) {
        cudaFuncSetAttribute(gemm_mma_kernel,
                             cudaFuncAttributeMaxDynamicSharedMemorySize,
                             GEMM_SMEM_BYTES);
        smem_set = true;
    }
    dim3 grid(N_PAD / 128, UNITS / 128);
    gemm_mma_kernel<<<grid, 256, GEMM_SMEM_BYTES>>>(out);
}

// round 4
// speedup vs baseline: 1.2011x; 1.0225x over previous
#include <cuda_runtime.h>
#include <cuda_bf16.h>
#include <cstdint>

#define N_NODES 50000
#define N_PAD   50048      // 391 * 128
#define N_EDGES 800000
#define D_FEAT  128
#define UNITS   256

// ---------------------------------------------------------------- scratch ---
__device__ float g_deg[N_NODES];          // sum of edge_val per row
__device__ int   g_cnt[N_NODES];          // edge count per row
__device__ int   g_fill[N_NODES];         // fill cursors
__device__ int   g_rowptr[N_NODES + 1];
__device__ int   g_cidx[N_EDGES];
__device__ float g_cval[N_EDGES];
__device__ float g_norm[(size_t)N_NODES * D_FEAT];
// bf16 split operands (zero-init; pad rows never written -> stay zero)
__device__ __nv_bfloat16 g_Ahi[(size_t)N_PAD * D_FEAT];
__device__ __nv_bfloat16 g_Alo[(size_t)N_PAD * D_FEAT];
__device__ __nv_bfloat16 g_Whi[(size_t)UNITS * D_FEAT];   // transposed: [n][k]
__device__ __nv_bfloat16 g_Wlo[(size_t)UNITS * D_FEAT];

// ------------------------------------------------------------- init+degree --
__global__ void zero_kernel() {
    int i = blockIdx.x * blockDim.x + threadIdx.x;
    if (i < N_NODES) {
        g_deg[i]  = 0.0f;
        g_cnt[i]  = 0;
        g_fill[i] = 0;
    }
}

__global__ void degree_kernel(const int* __restrict__ erow,
                              const float* __restrict__ eval) {
    int e = blockIdx.x * blockDim.x + threadIdx.x;
    if (e < N_EDGES) {
        int r = erow[e];
        atomicAdd(&g_deg[r], eval[e]);
        atomicAdd(&g_cnt[r], 1);
    }
}

// ------------------------------------------------------- rowptr scan (1 CTA)
__global__ void __launch_bounds__(1024) scan_kernel() {
    __shared__ int s[1024];
    const int T = 1024;
    const int tid = threadIdx.x;
    const int chunk = (N_NODES + T - 1) / T;      // 49
    const int start = tid * chunk;
    const int end   = min(start + chunk, N_NODES);

    int sum = 0;
    for (int i = start; i < end; i++) sum += g_cnt[i];
    s[tid] = sum;
    __syncthreads();
    for (int off = 1; off < T; off <<= 1) {
        int v = (tid >= off) ? s[tid - off] : 0;
        __syncthreads();
        if (tid >= off) s[tid] += v;
        __syncthreads();
    }
    int run = (tid > 0) ? s[tid - 1] : 0;
    for (int i = start; i < end; i++) {
        g_rowptr[i] = run;
        run += g_cnt[i];
    }
    if (tid == T - 1) g_rowptr[N_NODES] = run;
}

// ------------------------------------------------------------ CSR fill ------
__global__ void fill_kernel(const int* __restrict__ erow,
                            const int* __restrict__ ecol,
                            const float* __restrict__ eval) {
    int e = blockIdx.x * blockDim.x + threadIdx.x;
    if (e >= N_EDGES) return;
    int r = erow[e];
    int pos = g_rowptr[r] + atomicAdd(&g_fill[r], 1);
    g_cidx[pos] = ecol[e];
    g_cval[pos] = eval[e];
}

// --------------------------------------------------------- normalize --------
__global__ void normalize_kernel(const float* __restrict__ feat) {
    int idx = blockIdx.x * blockDim.x + threadIdx.x;   // float4 index
    const int total = N_NODES * (D_FEAT / 4);
    if (idx >= total) return;
    int n = idx >> 5;
    float inv = rsqrtf(g_deg[n] + 1.0f);
    float4 f = __ldg(((const float4*)feat) + idx);
    ((float4*)g_norm)[idx] =
        make_float4(f.x * inv, f.y * inv, f.z * inv, f.w * inv);
}

// ------------------------------------------------------------ bf16 split ----
__device__ __forceinline__ void bf16_split(float x, __nv_bfloat16& hi,
                                           __nv_bfloat16& lo) {
    hi = __float2bfloat16(x);
    lo = __float2bfloat16(x - __bfloat162float(hi));
}

// --------------------------------------------- gather SpMM + fused split ----
// One warp per row. acc = inv*norm[r] + sum_e val_e * norm[col_e].
// Epilogue writes bf16 hi/lo directly (split_A fused away).
__global__ void __launch_bounds__(256)
gather_kernel() {
    int warp = (blockIdx.x * blockDim.x + threadIdx.x) >> 5;
    int lane = threadIdx.x & 31;
    if (warp >= N_NODES) return;
    const int r = warp;

    float inv = rsqrtf(g_deg[r] + 1.0f);
    float4 sf = __ldg((const float4*)(g_norm + (size_t)r * D_FEAT) + lane);
    float4 acc = make_float4(inv * sf.x, inv * sf.y, inv * sf.z, inv * sf.w);

    int e   = g_rowptr[r];
    int end = g_rowptr[r + 1];

    for (; e + 4 <= end; e += 4) {
        int   c0 = g_cidx[e],     c1 = g_cidx[e + 1];
        int   c2 = g_cidx[e + 2], c3 = g_cidx[e + 3];
        float v0 = g_cval[e],     v1 = g_cval[e + 1];
        float v2 = g_cval[e + 2], v3 = g_cval[e + 3];
        float4 m0 = __ldg((const float4*)(g_norm + (size_t)c0 * D_FEAT) + lane);
        float4 m1 = __ldg((const float4*)(g_norm + (size_t)c1 * D_FEAT) + lane);
        float4 m2 = __ldg((const float4*)(g_norm + (size_t)c2 * D_FEAT) + lane);
        float4 m3 = __ldg((const float4*)(g_norm + (size_t)c3 * D_FEAT) + lane);
        acc.x = fmaf(v0, m0.x, acc.x); acc.y = fmaf(v0, m0.y, acc.y);
        acc.z = fmaf(v0, m0.z, acc.z); acc.w = fmaf(v0, m0.w, acc.w);
        acc.x = fmaf(v1, m1.x, acc.x); acc.y = fmaf(v1, m1.y, acc.y);
        acc.z = fmaf(v1, m1.z, acc.z); acc.w = fmaf(v1, m1.w, acc.w);
        acc.x = fmaf(v2, m2.x, acc.x); acc.y = fmaf(v2, m2.y, acc.y);
        acc.z = fmaf(v2, m2.z, acc.z); acc.w = fmaf(v2, m2.w, acc.w);
        acc.x = fmaf(v3, m3.x, acc.x); acc.y = fmaf(v3, m3.y, acc.y);
        acc.z = fmaf(v3, m3.z, acc.z); acc.w = fmaf(v3, m3.w, acc.w);
    }
    for (; e < end; e++) {
        int   c = g_cidx[e];
        float v = g_cval[e];
        float4 m = __ldg((const float4*)(g_norm + (size_t)c * D_FEAT) + lane);
        acc.x = fmaf(v, m.x, acc.x); acc.y = fmaf(v, m.y, acc.y);
        acc.z = fmaf(v, m.z, acc.z); acc.w = fmaf(v, m.w, acc.w);
    }

    // fused bf16 split
    __nv_bfloat16 h0, h1, h2, h3, l0, l1, l2, l3;
    bf16_split(acc.x, h0, l0);
    bf16_split(acc.y, h1, l1);
    bf16_split(acc.z, h2, l2);
    bf16_split(acc.w, h3, l3);
    union { __nv_bfloat162 b2[2]; uint2 u; } uh, ul;
    uh.b2[0] = __nv_bfloat162(h0, h1); uh.b2[1] = __nv_bfloat162(h2, h3);
    ul.b2[0] = __nv_bfloat162(l0, l1); ul.b2[1] = __nv_bfloat162(l2, l3);
    *(uint2*)(g_Ahi + (size_t)r * D_FEAT + lane * 4) = uh.u;
    *(uint2*)(g_Alo + (size_t)r * D_FEAT + lane * 4) = ul.u;
}

__global__ void split_W_kernel(const float* __restrict__ W) {
    int k = blockIdx.x;        // 0..127
    int n = threadIdx.x;       // 0..255
    float x = W[(size_t)k * UNITS + n];
    __nv_bfloat16 hi, lo;
    bf16_split(x, hi, lo);
    g_Whi[(size_t)n * D_FEAT + k] = hi;    // transposed [n][k]
    g_Wlo[(size_t)n * D_FEAT + k] = lo;
}

// ----------------------------------------------- mma.sync bf16x3 GEMM -------
#define AS_STRIDE 136   // bf16 elems per smem row (128 + 8 pad)

__global__ void __launch_bounds__(256)
gemm_mma_kernel(float* __restrict__ out) {
    extern __shared__ __nv_bfloat16 smem[];
    __nv_bfloat16* As = smem;                        // [128][AS_STRIDE]
    __nv_bfloat16* Bs = smem + 128 * AS_STRIDE;      // [128][AS_STRIDE], [n][k]

    const int tid  = threadIdx.x;
    const int wid  = tid >> 5;
    const int lane = tid & 31;
    const int g    = lane >> 2;
    const int tg   = lane & 3;
    const int wm   = (wid & 3) * 32;
    const int wn   = (wid >> 2) * 64;
    const int bm   = blockIdx.x * 128;
    const int bn   = blockIdx.y * 128;

    float acc[2][8][4];
    #pragma unroll
    for (int i = 0; i < 2; i++)
        #pragma unroll
        for (int j = 0; j < 8; j++)
            #pragma unroll
            for (int q = 0; q < 4; q++) acc[i][j][q] = 0.0f;

    const __nv_bfloat16* Asrc[3] = { g_Ahi, g_Alo, g_Ahi };
    const __nv_bfloat16* Bsrc[3] = { g_Whi, g_Whi, g_Wlo };

    for (int p = 0; p < 3; p++) {
        const uint4* Ag = (const uint4*)(Asrc[p] + (size_t)bm * D_FEAT);
        const uint4* Bg = (const uint4*)(Bsrc[p] + (size_t)bn * D_FEAT);
        #pragma unroll
        for (int i = tid; i < 2048; i += 256) {
            int r = i >> 4, c = i & 15;
            *(uint4*)(As + r * AS_STRIDE + c * 8) = __ldg(Ag + i);
        }
        #pragma unroll
        for (int i = tid; i < 2048; i += 256) {
            int r = i >> 4, c = i & 15;
            *(uint4*)(Bs + r * AS_STRIDE + c * 8) = __ldg(Bg + i);
        }
        __syncthreads();

        #pragma unroll
        for (int kk = 0; kk < D_FEAT; kk += 16) {
            uint32_t a[2][4];
            #pragma unroll
            for (int i = 0; i < 2; i++) {
                const __nv_bfloat16* base =
                    As + (wm + i * 16 + g) * AS_STRIDE + kk + tg * 2;
                a[i][0] = *(const uint32_t*)(base);
                a[i][1] = *(const uint32_t*)(base + 8 * AS_STRIDE);
                a[i][2] = *(const uint32_t*)(base + 8);
                a[i][3] = *(const uint32_t*)(base + 8 * AS_STRIDE + 8);
            }
            uint32_t b[8][2];
            #pragma unroll
            for (int j = 0; j < 8; j++) {
                const __nv_bfloat16* base =
                    Bs + (wn + j * 8 + g) * AS_STRIDE + kk + tg * 2;
                b[j][0] = *(const uint32_t*)(base);
                b[j][1] = *(const uint32_t*)(base + 8);
            }
            #pragma unroll
            for (int i = 0; i < 2; i++)
                #pragma unroll
                for (int j = 0; j < 8; j++) {
                    asm volatile(
                        "mma.sync.aligned.m16n8k16.row.col.f32.bf16.bf16.f32 "
                        "{%0,%1,%2,%3}, {%4,%5,%6,%7}, {%8,%9}, {%0,%1,%2,%3};"
                        : "+f"(acc[i][j][0]), "+f"(acc[i][j][1]),
                          "+f"(acc[i][j][2]), "+f"(acc[i][j][3])
                        : "r"(a[i][0]), "r"(a[i][1]), "r"(a[i][2]), "r"(a[i][3]),
                          "r"(b[j][0]), "r"(b[j][1]));
                }
        }
        __syncthreads();
    }

    #pragma unroll
    for (int i = 0; i < 2; i++) {
        int row0 = bm + wm + i * 16 + g;
        int row1 = row0 + 8;
        #pragma unroll
        for (int j = 0; j < 8; j++) {
            int col = bn + wn + j * 8 + tg * 2;
            if (row0 < N_NODES) {
                float2 o0 = make_float2(fmaxf(acc[i][j][0], 0.0f),
                                        fmaxf(acc[i][j][1], 0.0f));
                *(float2*)&out[(size_t)row0 * UNITS + col] = o0;
            }
            if (row1 < N_NODES) {
                float2 o1 = make_float2(fmaxf(acc[i][j][2], 0.0f),
                                        fmaxf(acc[i][j][3], 0.0f));
                *(float2*)&out[(size_t)row1 * UNITS + col] = o1;
            }
        }
    }
}

#define GEMM_SMEM_BYTES (2 * 128 * AS_STRIDE * 2)   // 69632

// ------------------------------------------------------------------ launch --
extern "C" void kernel_launch(void* const* d_in, const int* in_sizes, int n_in,
                              void* d_out, int out_size) {
    const float* features = (const float*)d_in[0];
    const int*   edge_row = (const int*)d_in[1];
    const int*   edge_col = (const int*)d_in[2];
    const float* edge_val = (const float*)d_in[3];
    const float* W        = (const float*)d_in[4];
    float*       out      = (float*)d_out;

    zero_kernel<<<(N_NODES + 255) / 256, 256>>>();
    degree_kernel<<<(N_EDGES + 255) / 256, 256>>>(edge_row, edge_val);
    scan_kernel<<<1, 1024>>>();
    fill_kernel<<<(N_EDGES + 255) / 256, 256>>>(edge_row, edge_col, edge_val);

    const int nf4 = N_NODES * (D_FEAT / 4);
    normalize_kernel<<<(nf4 + 255) / 256, 256>>>(features);

    // one warp per row
    gather_kernel<<<(N_NODES * 32 + 255) / 256, 256>>>();

    split_W_kernel<<<D_FEAT, UNITS>>>(W);

    static bool smem_set = false;
    if (!smem_set) {
        cudaFuncSetAttribute(gemm_mma_kernel,
                             cudaFuncAttributeMaxDynamicSharedMemorySize,
                             GEMM_SMEM_BYTES);
        smem_set = true;
    }
    dim3 grid(N_PAD / 128, UNITS / 128);
    gemm_mma_kernel<<<grid, 256, GEMM_SMEM_BYTES>>>(out);
}

// round 5
// speedup vs baseline: 1.2177x; 1.0138x over previous
#include <cuda_runtime.h>
#include <cuda_bf16.h>
#include <cstdint>

#define N_NODES 50000
#define N_PAD   50048      // 391 * 128
#define N_EDGES 800000
#define D_FEAT  128
#define UNITS   256

// ---------------------------------------------------------------- scratch ---
__device__ float g_deg[N_NODES];          // sum of edge_val per row
__device__ int   g_cnt[N_NODES];          // edge count per row
__device__ int   g_fill[N_NODES];         // fill cursors
__device__ int   g_rowptr[N_NODES + 1];
__device__ int2  g_edge[N_EDGES];         // {col, val-bits} interleaved
__device__ float g_norm[(size_t)N_NODES * D_FEAT];
// bf16 split operands (zero-init; pad rows never written -> stay zero)
__device__ __nv_bfloat16 g_Ahi[(size_t)N_PAD * D_FEAT];
__device__ __nv_bfloat16 g_Alo[(size_t)N_PAD * D_FEAT];
__device__ __nv_bfloat16 g_Whi[(size_t)UNITS * D_FEAT];   // transposed: [n][k]
__device__ __nv_bfloat16 g_Wlo[(size_t)UNITS * D_FEAT];

// ------------------------------------------------------------- init+degree --
__global__ void zero_kernel() {
    int i = blockIdx.x * blockDim.x + threadIdx.x;
    if (i < N_NODES) {
        g_deg[i]  = 0.0f;
        g_cnt[i]  = 0;
        g_fill[i] = 0;
    }
}

__global__ void degree_kernel(const int* __restrict__ erow,
                              const float* __restrict__ eval) {
    int e = blockIdx.x * blockDim.x + threadIdx.x;
    if (e < N_EDGES) {
        int r = erow[e];
        atomicAdd(&g_deg[r], eval[e]);
        atomicAdd(&g_cnt[r], 1);
    }
}

// ------------------------------------------------------- rowptr scan (1 CTA)
__global__ void __launch_bounds__(1024) scan_kernel() {
    __shared__ int s[1024];
    const int T = 1024;
    const int tid = threadIdx.x;
    const int chunk = (N_NODES + T - 1) / T;      // 49
    const int start = tid * chunk;
    const int end   = min(start + chunk, N_NODES);

    int sum = 0;
    for (int i = start; i < end; i++) sum += g_cnt[i];
    s[tid] = sum;
    __syncthreads();
    for (int off = 1; off < T; off <<= 1) {
        int v = (tid >= off) ? s[tid - off] : 0;
        __syncthreads();
        if (tid >= off) s[tid] += v;
        __syncthreads();
    }
    int run = (tid > 0) ? s[tid - 1] : 0;
    for (int i = start; i < end; i++) {
        g_rowptr[i] = run;
        run += g_cnt[i];
    }
    if (tid == T - 1) g_rowptr[N_NODES] = run;
}

// ------------------------------------------------------------ CSR fill ------
__global__ void fill_kernel(const int* __restrict__ erow,
                            const int* __restrict__ ecol,
                            const float* __restrict__ eval) {
    int e = blockIdx.x * blockDim.x + threadIdx.x;
    if (e >= N_EDGES) return;
    int r = erow[e];
    int pos = g_rowptr[r] + atomicAdd(&g_fill[r], 1);
    g_edge[pos] = make_int2(ecol[e], __float_as_int(eval[e]));
}

// --------------------------------------------------------- normalize --------
__global__ void normalize_kernel(const float* __restrict__ feat) {
    int idx = blockIdx.x * blockDim.x + threadIdx.x;   // float4 index
    const int total = N_NODES * (D_FEAT / 4);
    if (idx >= total) return;
    int n = idx >> 5;
    float inv = rsqrtf(g_deg[n] + 1.0f);
    float4 f = __ldg(((const float4*)feat) + idx);
    ((float4*)g_norm)[idx] =
        make_float4(f.x * inv, f.y * inv, f.z * inv, f.w * inv);
}

// ------------------------------------------------------------ bf16 split ----
__device__ __forceinline__ void bf16_split(float x, __nv_bfloat16& hi,
                                           __nv_bfloat16& lo) {
    hi = __float2bfloat16(x);
    lo = __float2bfloat16(x - __bfloat162float(hi));
}

// --------------------------------------------- gather SpMM + fused split ----
// One warp per row. 32-edge chunks prefetched cooperatively (one int2/lane),
// indices broadcast via shfl, gathers issued in batches of 8 for MLP.
__global__ void __launch_bounds__(256)
gather_kernel() {
    int warp = (blockIdx.x * blockDim.x + threadIdx.x) >> 5;
    int lane = threadIdx.x & 31;
    if (warp >= N_NODES) return;
    const int r = warp;

    float inv = rsqrtf(g_deg[r] + 1.0f);
    float4 sf = __ldg((const float4*)(g_norm + (size_t)r * D_FEAT) + lane);
    float4 acc = make_float4(inv * sf.x, inv * sf.y, inv * sf.z, inv * sf.w);

    const int beg = g_rowptr[r];
    const int deg = g_rowptr[r + 1] - beg;

    int done = 0;
    while (done < deg) {
        const int chunk = min(32, deg - done);
        int2 ev = make_int2(0, 0);
        if (lane < chunk) ev = __ldg(&g_edge[beg + done + lane]);

        int d = 0;
        for (; d + 8 <= chunk; d += 8) {
            int   cs[8];
            float vs[8];
            #pragma unroll
            for (int j = 0; j < 8; j++) {
                cs[j] = __shfl_sync(0xffffffffu, ev.x, d + j);
                vs[j] = __uint_as_float(__shfl_sync(0xffffffffu, ev.y, d + j));
            }
            float4 ms[8];
            #pragma unroll
            for (int j = 0; j < 8; j++)
                ms[j] = __ldg((const float4*)(g_norm + (size_t)cs[j] * D_FEAT) + lane);
            #pragma unroll
            for (int j = 0; j < 8; j++) {
                acc.x = fmaf(vs[j], ms[j].x, acc.x);
                acc.y = fmaf(vs[j], ms[j].y, acc.y);
                acc.z = fmaf(vs[j], ms[j].z, acc.z);
                acc.w = fmaf(vs[j], ms[j].w, acc.w);
            }
        }
        for (; d < chunk; d++) {
            int   c = __shfl_sync(0xffffffffu, ev.x, d);
            float v = __uint_as_float(__shfl_sync(0xffffffffu, ev.y, d));
            float4 m = __ldg((const float4*)(g_norm + (size_t)c * D_FEAT) + lane);
            acc.x = fmaf(v, m.x, acc.x); acc.y = fmaf(v, m.y, acc.y);
            acc.z = fmaf(v, m.z, acc.z); acc.w = fmaf(v, m.w, acc.w);
        }
        done += chunk;
    }

    // fused bf16 split
    __nv_bfloat16 h0, h1, h2, h3, l0, l1, l2, l3;
    bf16_split(acc.x, h0, l0);
    bf16_split(acc.y, h1, l1);
    bf16_split(acc.z, h2, l2);
    bf16_split(acc.w, h3, l3);
    union { __nv_bfloat162 b2[2]; uint2 u; } uh, ul;
    uh.b2[0] = __nv_bfloat162(h0, h1); uh.b2[1] = __nv_bfloat162(h2, h3);
    ul.b2[0] = __nv_bfloat162(l0, l1); ul.b2[1] = __nv_bfloat162(l2, l3);
    *(uint2*)(g_Ahi + (size_t)r * D_FEAT + lane * 4) = uh.u;
    *(uint2*)(g_Alo + (size_t)r * D_FEAT + lane * 4) = ul.u;
}

__global__ void split_W_kernel(const float* __restrict__ W) {
    int k = blockIdx.x;        // 0..127
    int n = threadIdx.x;       // 0..255
    float x = W[(size_t)k * UNITS + n];
    __nv_bfloat16 hi, lo;
    bf16_split(x, hi, lo);
    g_Whi[(size_t)n * D_FEAT + k] = hi;    // transposed [n][k]
    g_Wlo[(size_t)n * D_FEAT + k] = lo;
}

// ----------------------------------------------- mma.sync bf16x3 GEMM -------
#define AS_STRIDE 136   // bf16 elems per smem row (128 + 8 pad)

__global__ void __launch_bounds__(256)
gemm_mma_kernel(float* __restrict__ out) {
    extern __shared__ __nv_bfloat16 smem[];
    __nv_bfloat16* As = smem;                        // [128][AS_STRIDE]
    __nv_bfloat16* Bs = smem + 128 * AS_STRIDE;      // [128][AS_STRIDE], [n][k]

    const int tid  = threadIdx.x;
    const int wid  = tid >> 5;
    const int lane = tid & 31;
    const int g    = lane >> 2;
    const int tg   = lane & 3;
    const int wm   = (wid & 3) * 32;
    const int wn   = (wid >> 2) * 64;
    const int bm   = blockIdx.x * 128;
    const int bn   = blockIdx.y * 128;

    float acc[2][8][4];
    #pragma unroll
    for (int i = 0; i < 2; i++)
        #pragma unroll
        for (int j = 0; j < 8; j++)
            #pragma unroll
            for (int q = 0; q < 4; q++) acc[i][j][q] = 0.0f;

    const __nv_bfloat16* Asrc[3] = { g_Ahi, g_Alo, g_Ahi };
    const __nv_bfloat16* Bsrc[3] = { g_Whi, g_Whi, g_Wlo };

    for (int p = 0; p < 3; p++) {
        const uint4* Ag = (const uint4*)(Asrc[p] + (size_t)bm * D_FEAT);
        const uint4* Bg = (const uint4*)(Bsrc[p] + (size_t)bn * D_FEAT);
        #pragma unroll
        for (int i = tid; i < 2048; i += 256) {
            int r = i >> 4, c = i & 15;
            *(uint4*)(As + r * AS_STRIDE + c * 8) = __ldg(Ag + i);
        }
        #pragma unroll
        for (int i = tid; i < 2048; i += 256) {
            int r = i >> 4, c = i & 15;
            *(uint4*)(Bs + r * AS_STRIDE + c * 8) = __ldg(Bg + i);
        }
        __syncthreads();

        #pragma unroll
        for (int kk = 0; kk < D_FEAT; kk += 16) {
            uint32_t a[2][4];
            #pragma unroll
            for (int i = 0; i < 2; i++) {
                const __nv_bfloat16* base =
                    As + (wm + i * 16 + g) * AS_STRIDE + kk + tg * 2;
                a[i][0] = *(const uint32_t*)(base);
                a[i][1] = *(const uint32_t*)(base + 8 * AS_STRIDE);
                a[i][2] = *(const uint32_t*)(base + 8);
                a[i][3] = *(const uint32_t*)(base + 8 * AS_STRIDE + 8);
            }
            uint32_t b[8][2];
            #pragma unroll
            for (int j = 0; j < 8; j++) {
                const __nv_bfloat16* base =
                    Bs + (wn + j * 8 + g) * AS_STRIDE + kk + tg * 2;
                b[j][0] = *(const uint32_t*)(base);
                b[j][1] = *(const uint32_t*)(base + 8);
            }
            #pragma unroll
            for (int i = 0; i < 2; i++)
                #pragma unroll
                for (int j = 0; j < 8; j++) {
                    asm volatile(
                        "mma.sync.aligned.m16n8k16.row.col.f32.bf16.bf16.f32 "
                        "{%0,%1,%2,%3}, {%4,%5,%6,%7}, {%8,%9}, {%0,%1,%2,%3};"
                        : "+f"(acc[i][j][0]), "+f"(acc[i][j][1]),
                          "+f"(acc[i][j][2]), "+f"(acc[i][j][3])
                        : "r"(a[i][0]), "r"(a[i][1]), "r"(a[i][2]), "r"(a[i][3]),
                          "r"(b[j][0]), "r"(b[j][1]));
                }
        }
        __syncthreads();
    }

    #pragma unroll
    for (int i = 0; i < 2; i++) {
        int row0 = bm + wm + i * 16 + g;
        int row1 = row0 + 8;
        #pragma unroll
        for (int j = 0; j < 8; j++) {
            int col = bn + wn + j * 8 + tg * 2;
            if (row0 < N_NODES) {
                float2 o0 = make_float2(fmaxf(acc[i][j][0], 0.0f),
                                        fmaxf(acc[i][j][1], 0.0f));
                *(float2*)&out[(size_t)row0 * UNITS + col] = o0;
            }
            if (row1 < N_NODES) {
                float2 o1 = make_float2(fmaxf(acc[i][j][2], 0.0f),
                                        fmaxf(acc[i][j][3], 0.0f));
                *(float2*)&out[(size_t)row1 * UNITS + col] = o1;
            }
        }
    }
}

#define GEMM_SMEM_BYTES (2 * 128 * AS_STRIDE * 2)   // 69632

// ------------------------------------------------------------------ launch --
extern "C" void kernel_launch(void* const* d_in, const int* in_sizes, int n_in,
                              void* d_out, int out_size) {
    const float* features = (const float*)d_in[0];
    const int*   edge_row = (const int*)d_in[1];
    const int*   edge_col = (const int*)d_in[2];
    const float* edge_val = (const float*)d_in[3];
    const float* W        = (const float*)d_in[4];
    float*       out      = (float*)d_out;

    zero_kernel<<<(N_NODES + 255) / 256, 256>>>();
    degree_kernel<<<(N_EDGES + 255) / 256, 256>>>(edge_row, edge_val);
    scan_kernel<<<1, 1024>>>();
    fill_kernel<<<(N_EDGES + 255) / 256, 256>>>(edge_row, edge_col, edge_val);

    const int nf4 = N_NODES * (D_FEAT / 4);
    normalize_kernel<<<(nf4 + 255) / 256, 256>>>(features);

    // one warp per row
    gather_kernel<<<(N_NODES * 32 + 255) / 256, 256>>>();

    split_W_kernel<<<D_FEAT, UNITS>>>(W);

    static bool smem_set = false;
    if (!smem_set) {
        cudaFuncSetAttribute(gemm_mma_kernel,
                             cudaFuncAttributeMaxDynamicSharedMemorySize,
                             GEMM_SMEM_BYTES);
        smem_set = true;
    }
    dim3 grid(N_PAD / 128, UNITS / 128);
    gemm_mma_kernel<<<grid, 256, GEMM_SMEM_BYTES>>>(out);
}

// round 6
// speedup vs baseline: 1.9420x; 1.5948x over previous
#include <cuda_runtime.h>
#include <cuda_bf16.h>
#include <cuda_fp16.h>
#include <cstdint>

#define N_NODES 50000
#define N_PAD   50048      // 391 * 128
#define N_EDGES 800000
#define D_FEAT  128
#define UNITS   256
#define ELLW    80         // padded ELL width (max degree ~35 whp)

// ---------------------------------------------------------------- scratch ---
__device__ unsigned long long g_pack[N_NODES];  // count<<42 | fix24(val sum)
__device__ int    g_cnt[N_NODES];
__device__ float  g_invd[N_NODES];
__device__ int2   g_ell[(size_t)N_NODES * ELLW];   // {col, val-bits}
__device__ __half g_normh[(size_t)N_NODES * D_FEAT];
// bf16 split operands (zero-init; pad rows never written -> stay zero)
__device__ __nv_bfloat16 g_Ahi[(size_t)N_PAD * D_FEAT];
__device__ __nv_bfloat16 g_Alo[(size_t)N_PAD * D_FEAT];
__device__ __nv_bfloat16 g_Whi[(size_t)UNITS * D_FEAT];   // transposed: [n][k]
__device__ __nv_bfloat16 g_Wlo[(size_t)UNITS * D_FEAT];

// -------------------------------------------------------------------- zero --
__global__ void zero_kernel() {
    int i = blockIdx.x * blockDim.x + threadIdx.x;
    if (i < N_NODES) g_pack[i] = 0ull;
}

// ---------------------------------------- fused degree + count + ELL fill ---
// One 64-bit atomic per edge: returns slot AND accumulates degree sum.
__global__ void fill_ell_kernel(const int* __restrict__ erow,
                                const int* __restrict__ ecol,
                                const float* __restrict__ eval) {
    int e = blockIdx.x * blockDim.x + threadIdx.x;
    if (e >= N_EDGES) return;
    int   r = erow[e];
    float v = eval[e];
    unsigned long long q =
        (1ull << 42) + (unsigned long long)(v * 16777216.0f);
    unsigned long long old = atomicAdd(&g_pack[r], q);
    int slot = (int)(old >> 42);
    g_ell[(size_t)r * ELLW + slot] = make_int2(ecol[e], __float_as_int(v));
}

// -------------------------------------------------------------- invd --------
__global__ void invd_kernel() {
    int i = blockIdx.x * blockDim.x + threadIdx.x;
    if (i >= N_NODES) return;
    unsigned long long p = g_pack[i];
    g_cnt[i] = (int)(p >> 42);
    float deg = (float)(p & ((1ull << 42) - 1)) * (1.0f / 16777216.0f);
    g_invd[i] = rsqrtf(deg + 1.0f);
}

// ---------------------------------------------- normalize -> fp16 -----------
__global__ void normalize_kernel(const float* __restrict__ feat) {
    int idx = blockIdx.x * blockDim.x + threadIdx.x;   // uint2 (4 halves) index
    const int total = N_NODES * (D_FEAT / 4);
    if (idx >= total) return;
    int n = idx >> 5;
    float inv = g_invd[n];
    float4 f = __ldg(((const float4*)feat) + idx);
    __half2 a = __floats2half2_rn(f.x * inv, f.y * inv);
    __half2 b = __floats2half2_rn(f.z * inv, f.w * inv);
    union { __half2 h[2]; uint2 u; } u;
    u.h[0] = a; u.h[1] = b;
    ((uint2*)g_normh)[idx] = u.u;
}

// ------------------------------------------------------------ bf16 split ----
__device__ __forceinline__ void bf16_split(float x, __nv_bfloat16& hi,
                                           __nv_bfloat16& lo) {
    hi = __float2bfloat16(x);
    lo = __float2bfloat16(x - __bfloat162float(hi));
}

// --------------------------------------------- gather SpMM + fused split ----
// One warp per row; fp16 gathered rows (256B/edge); self term from fp32 feat.
__global__ void __launch_bounds__(256)
gather_kernel(const float* __restrict__ feat) {
    int warp = (blockIdx.x * blockDim.x + threadIdx.x) >> 5;
    int lane = threadIdx.x & 31;
    if (warp >= N_NODES) return;
    const int r = warp;

    float inv  = g_invd[r];
    float inv2 = inv * inv;
    float4 sf = __ldg((const float4*)(feat + (size_t)r * D_FEAT) + lane);
    float4 acc = make_float4(inv2 * sf.x, inv2 * sf.y, inv2 * sf.z, inv2 * sf.w);

    const int deg = g_cnt[r];
    const int2* ebase = g_ell + (size_t)r * ELLW;

    int done = 0;
    while (done < deg) {
        const int chunk = min(32, deg - done);
        int2 ev = make_int2(0, 0);
        if (lane < chunk) ev = __ldg(ebase + done + lane);

        int d = 0;
        for (; d + 8 <= chunk; d += 8) {
            int   cs[8];
            float vs[8];
            #pragma unroll
            for (int j = 0; j < 8; j++) {
                cs[j] = __shfl_sync(0xffffffffu, ev.x, d + j);
                vs[j] = __uint_as_float(__shfl_sync(0xffffffffu, ev.y, d + j));
            }
            uint2 ms[8];
            #pragma unroll
            for (int j = 0; j < 8; j++)
                ms[j] = __ldg((const uint2*)(g_normh + (size_t)cs[j] * D_FEAT) + lane);
            #pragma unroll
            for (int j = 0; j < 8; j++) {
                union { uint2 u; __half2 h[2]; } m; m.u = ms[j];
                float2 f01 = __half22float2(m.h[0]);
                float2 f23 = __half22float2(m.h[1]);
                acc.x = fmaf(vs[j], f01.x, acc.x);
                acc.y = fmaf(vs[j], f01.y, acc.y);
                acc.z = fmaf(vs[j], f23.x, acc.z);
                acc.w = fmaf(vs[j], f23.y, acc.w);
            }
        }
        for (; d < chunk; d++) {
            int   c = __shfl_sync(0xffffffffu, ev.x, d);
            float v = __uint_as_float(__shfl_sync(0xffffffffu, ev.y, d));
            union { uint2 u; __half2 h[2]; } m;
            m.u = __ldg((const uint2*)(g_normh + (size_t)c * D_FEAT) + lane);
            float2 f01 = __half22float2(m.h[0]);
            float2 f23 = __half22float2(m.h[1]);
            acc.x = fmaf(v, f01.x, acc.x);
            acc.y = fmaf(v, f01.y, acc.y);
            acc.z = fmaf(v, f23.x, acc.z);
            acc.w = fmaf(v, f23.y, acc.w);
        }
        done += chunk;
    }

    // fused bf16 split
    __nv_bfloat16 h0, h1, h2, h3, l0, l1, l2, l3;
    bf16_split(acc.x, h0, l0);
    bf16_split(acc.y, h1, l1);
    bf16_split(acc.z, h2, l2);
    bf16_split(acc.w, h3, l3);
    union { __nv_bfloat162 b2[2]; uint2 u; } uh, ul;
    uh.b2[0] = __nv_bfloat162(h0, h1); uh.b2[1] = __nv_bfloat162(h2, h3);
    ul.b2[0] = __nv_bfloat162(l0, l1); ul.b2[1] = __nv_bfloat162(l2, l3);
    *(uint2*)(g_Ahi + (size_t)r * D_FEAT + lane * 4) = uh.u;
    *(uint2*)(g_Alo + (size_t)r * D_FEAT + lane * 4) = ul.u;
}

__global__ void split_W_kernel(const float* __restrict__ W) {
    int k = blockIdx.x;        // 0..127
    int n = threadIdx.x;       // 0..255
    float x = W[(size_t)k * UNITS + n];
    __nv_bfloat16 hi, lo;
    bf16_split(x, hi, lo);
    g_Whi[(size_t)n * D_FEAT + k] = hi;    // transposed [n][k]
    g_Wlo[(size_t)n * D_FEAT + k] = lo;
}

// ----------------------------------------------- mma.sync bf16x3 GEMM -------
#define AS_STRIDE 136   // bf16 elems per smem row (128 + 8 pad)

__global__ void __launch_bounds__(256)
gemm_mma_kernel(float* __restrict__ out) {
    extern __shared__ __nv_bfloat16 smem[];
    __nv_bfloat16* As = smem;                        // [128][AS_STRIDE]
    __nv_bfloat16* Bs = smem + 128 * AS_STRIDE;      // [128][AS_STRIDE], [n][k]

    const int tid  = threadIdx.x;
    const int wid  = tid >> 5;
    const int lane = tid & 31;
    const int g    = lane >> 2;
    const int tg   = lane & 3;
    const int wm   = (wid & 3) * 32;
    const int wn   = (wid >> 2) * 64;
    const int bm   = blockIdx.x * 128;
    const int bn   = blockIdx.y * 128;

    float acc[2][8][4];
    #pragma unroll
    for (int i = 0; i < 2; i++)
        #pragma unroll
        for (int j = 0; j < 8; j++)
            #pragma unroll
            for (int q = 0; q < 4; q++) acc[i][j][q] = 0.0f;

    const __nv_bfloat16* Asrc[3] = { g_Ahi, g_Alo, g_Ahi };
    const __nv_bfloat16* Bsrc[3] = { g_Whi, g_Whi, g_Wlo };

    for (int p = 0; p < 3; p++) {
        const uint4* Ag = (const uint4*)(Asrc[p] + (size_t)bm * D_FEAT);
        const uint4* Bg = (const uint4*)(Bsrc[p] + (size_t)bn * D_FEAT);
        #pragma unroll
        for (int i = tid; i < 2048; i += 256) {
            int r = i >> 4, c = i & 15;
            *(uint4*)(As + r * AS_STRIDE + c * 8) = __ldg(Ag + i);
        }
        #pragma unroll
        for (int i = tid; i < 2048; i += 256) {
            int r = i >> 4, c = i & 15;
            *(uint4*)(Bs + r * AS_STRIDE + c * 8) = __ldg(Bg + i);
        }
        __syncthreads();

        #pragma unroll
        for (int kk = 0; kk < D_FEAT; kk += 16) {
            uint32_t a[2][4];
            #pragma unroll
            for (int i = 0; i < 2; i++) {
                const __nv_bfloat16* base =
                    As + (wm + i * 16 + g) * AS_STRIDE + kk + tg * 2;
                a[i][0] = *(const uint32_t*)(base);
                a[i][1] = *(const uint32_t*)(base + 8 * AS_STRIDE);
                a[i][2] = *(const uint32_t*)(base + 8);
                a[i][3] = *(const uint32_t*)(base + 8 * AS_STRIDE + 8);
            }
            uint32_t b[8][2];
            #pragma unroll
            for (int j = 0; j < 8; j++) {
                const __nv_bfloat16* base =
                    Bs + (wn + j * 8 + g) * AS_STRIDE + kk + tg * 2;
                b[j][0] = *(const uint32_t*)(base);
                b[j][1] = *(const uint32_t*)(base + 8);
            }
            #pragma unroll
            for (int i = 0; i < 2; i++)
                #pragma unroll
                for (int j = 0; j < 8; j++) {
                    asm volatile(
                        "mma.sync.aligned.m16n8k16.row.col.f32.bf16.bf16.f32 "
                        "{%0,%1,%2,%3}, {%4,%5,%6,%7}, {%8,%9}, {%0,%1,%2,%3};"
                        : "+f"(acc[i][j][0]), "+f"(acc[i][j][1]),
                          "+f"(acc[i][j][2]), "+f"(acc[i][j][3])
                        : "r"(a[i][0]), "r"(a[i][1]), "r"(a[i][2]), "r"(a[i][3]),
                          "r"(b[j][0]), "r"(b[j][1]));
                }
        }
        __syncthreads();
    }

    #pragma unroll
    for (int i = 0; i < 2; i++) {
        int row0 = bm + wm + i * 16 + g;
        int row1 = row0 + 8;
        #pragma unroll
        for (int j = 0; j < 8; j++) {
            int col = bn + wn + j * 8 + tg * 2;
            if (row0 < N_NODES) {
                float2 o0 = make_float2(fmaxf(acc[i][j][0], 0.0f),
                                        fmaxf(acc[i][j][1], 0.0f));
                *(float2*)&out[(size_t)row0 * UNITS + col] = o0;
            }
            if (row1 < N_NODES) {
                float2 o1 = make_float2(fmaxf(acc[i][j][2], 0.0f),
                                        fmaxf(acc[i][j][3], 0.0f));
                *(float2*)&out[(size_t)row1 * UNITS + col] = o1;
            }
        }
    }
}

#define GEMM_SMEM_BYTES (2 * 128 * AS_STRIDE * 2)   // 69632

// ------------------------------------------------------------------ launch --
extern "C" void kernel_launch(void* const* d_in, const int* in_sizes, int n_in,
                              void* d_out, int out_size) {
    const float* features = (const float*)d_in[0];
    const int*   edge_row = (const int*)d_in[1];
    const int*   edge_col = (const int*)d_in[2];
    const float* edge_val = (const float*)d_in[3];
    const float* W        = (const float*)d_in[4];
    float*       out      = (float*)d_out;

    zero_kernel<<<(N_NODES + 255) / 256, 256>>>();
    fill_ell_kernel<<<(N_EDGES + 255) / 256, 256>>>(edge_row, edge_col, edge_val);
    invd_kernel<<<(N_NODES + 255) / 256, 256>>>();

    const int nf4 = N_NODES * (D_FEAT / 4);
    normalize_kernel<<<(nf4 + 255) / 256, 256>>>(features);

    // one warp per row
    gather_kernel<<<(N_NODES * 32 + 255) / 256, 256>>>(features);

    split_W_kernel<<<D_FEAT, UNITS>>>(W);

    static bool smem_set = false;
    if (!smem_set) {
        cudaFuncSetAttribute(gemm_mma_kernel,
                             cudaFuncAttributeMaxDynamicSharedMemorySize,
                             GEMM_SMEM_BYTES);
        smem_set = true;
    }
    dim3 grid(N_PAD / 128, UNITS / 128);
    gemm_mma_kernel<<<grid, 256, GEMM_SMEM_BYTES>>>(out);
}

// round 7
// speedup vs baseline: 1.9728x; 1.0159x over previous
#include <cuda_runtime.h>
#include <cuda_bf16.h>
#include <cuda_fp16.h>
#include <cstdint>

#define N_NODES 50000
#define N_PAD   50048      // 391 * 128
#define N_EDGES 800000
#define D_FEAT  128
#define UNITS   256
#define ELLW    80         // padded ELL width (max degree ~35 whp)

// ---------------------------------------------------------------- scratch ---
__device__ unsigned long long g_pack[N_NODES];  // count<<42 | fix24(val sum)
__device__ int2   g_ell[(size_t)N_NODES * ELLW];   // {col, val-bits}
__device__ __half g_normh[(size_t)N_NODES * D_FEAT];
// bf16 split operands (zero-init; pad rows never written -> stay zero)
__device__ __nv_bfloat16 g_Ahi[(size_t)N_PAD * D_FEAT];
__device__ __nv_bfloat16 g_Alo[(size_t)N_PAD * D_FEAT];
__device__ __nv_bfloat16 g_Whi[(size_t)UNITS * D_FEAT];   // transposed: [n][k]
__device__ __nv_bfloat16 g_Wlo[(size_t)UNITS * D_FEAT];

// -------------------------------------------------------------------- zero --
__global__ void zero_kernel() {
    int i = blockIdx.x * blockDim.x + threadIdx.x;
    if (i < N_NODES) g_pack[i] = 0ull;
}

// ---------------------------------------- fused degree + count + ELL fill ---
__global__ void fill_ell_kernel(const int* __restrict__ erow,
                                const int* __restrict__ ecol,
                                const float* __restrict__ eval) {
    int e = blockIdx.x * blockDim.x + threadIdx.x;
    if (e >= N_EDGES) return;
    int   r = erow[e];
    float v = eval[e];
    unsigned long long q =
        (1ull << 42) + (unsigned long long)(v * 16777216.0f);
    unsigned long long old = atomicAdd(&g_pack[r], q);
    int slot = (int)(old >> 42);
    g_ell[(size_t)r * ELLW + slot] = make_int2(ecol[e], __float_as_int(v));
}

__device__ __forceinline__ float pack_to_inv(unsigned long long p) {
    float deg = (float)(p & ((1ull << 42) - 1)) * (1.0f / 16777216.0f);
    return rsqrtf(deg + 1.0f);
}

// ---------------------------------------------- normalize -> fp16 -----------
__global__ void normalize_kernel(const float* __restrict__ feat) {
    int idx = blockIdx.x * blockDim.x + threadIdx.x;   // 4-elem index
    const int total = N_NODES * (D_FEAT / 4);
    if (idx >= total) return;
    int n = idx >> 5;
    float inv = pack_to_inv(g_pack[n]);
    float4 f = __ldg(((const float4*)feat) + idx);
    __half2 a = __floats2half2_rn(f.x * inv, f.y * inv);
    __half2 b = __floats2half2_rn(f.z * inv, f.w * inv);
    union { __half2 h[2]; uint2 u; } u;
    u.h[0] = a; u.h[1] = b;
    ((uint2*)g_normh)[idx] = u.u;
}

// ------------------------------------------------------------ bf16 split ----
__device__ __forceinline__ void bf16_split(float x, __nv_bfloat16& hi,
                                           __nv_bfloat16& lo) {
    hi = __float2bfloat16(x);
    lo = __float2bfloat16(x - __bfloat162float(hi));
}

// --------------------------------------------- gather SpMM + fused split ----
__global__ void __launch_bounds__(256)
gather_kernel(const float* __restrict__ feat) {
    int warp = (blockIdx.x * blockDim.x + threadIdx.x) >> 5;
    int lane = threadIdx.x & 31;
    if (warp >= N_NODES) return;
    const int r = warp;

    unsigned long long p = g_pack[r];
    const int deg = (int)(p >> 42);
    float inv  = pack_to_inv(p);
    float inv2 = inv * inv;
    float4 sf = __ldg((const float4*)(feat + (size_t)r * D_FEAT) + lane);
    float4 acc = make_float4(inv2 * sf.x, inv2 * sf.y, inv2 * sf.z, inv2 * sf.w);

    const int2* ebase = g_ell + (size_t)r * ELLW;

    int done = 0;
    while (done < deg) {
        const int chunk = min(32, deg - done);
        int2 ev = make_int2(0, 0);
        if (lane < chunk) ev = __ldg(ebase + done + lane);

        int d = 0;
        for (; d + 8 <= chunk; d += 8) {
            int   cs[8];
            float vs[8];
            #pragma unroll
            for (int j = 0; j < 8; j++) {
                cs[j] = __shfl_sync(0xffffffffu, ev.x, d + j);
                vs[j] = __uint_as_float(__shfl_sync(0xffffffffu, ev.y, d + j));
            }
            uint2 ms[8];
            #pragma unroll
            for (int j = 0; j < 8; j++)
                ms[j] = __ldg((const uint2*)(g_normh + (size_t)cs[j] * D_FEAT) + lane);
            #pragma unroll
            for (int j = 0; j < 8; j++) {
                union { uint2 u; __half2 h[2]; } m; m.u = ms[j];
                float2 f01 = __half22float2(m.h[0]);
                float2 f23 = __half22float2(m.h[1]);
                acc.x = fmaf(vs[j], f01.x, acc.x);
                acc.y = fmaf(vs[j], f01.y, acc.y);
                acc.z = fmaf(vs[j], f23.x, acc.z);
                acc.w = fmaf(vs[j], f23.y, acc.w);
            }
        }
        for (; d < chunk; d++) {
            int   c = __shfl_sync(0xffffffffu, ev.x, d);
            float v = __uint_as_float(__shfl_sync(0xffffffffu, ev.y, d));
            union { uint2 u; __half2 h[2]; } m;
            m.u = __ldg((const uint2*)(g_normh + (size_t)c * D_FEAT) + lane);
            float2 f01 = __half22float2(m.h[0]);
            float2 f23 = __half22float2(m.h[1]);
            acc.x = fmaf(v, f01.x, acc.x);
            acc.y = fmaf(v, f01.y, acc.y);
            acc.z = fmaf(v, f23.x, acc.z);
            acc.w = fmaf(v, f23.y, acc.w);
        }
        done += chunk;
    }

    __nv_bfloat16 h0, h1, h2, h3, l0, l1, l2, l3;
    bf16_split(acc.x, h0, l0);
    bf16_split(acc.y, h1, l1);
    bf16_split(acc.z, h2, l2);
    bf16_split(acc.w, h3, l3);
    union { __nv_bfloat162 b2[2]; uint2 u; } uh, ul;
    uh.b2[0] = __nv_bfloat162(h0, h1); uh.b2[1] = __nv_bfloat162(h2, h3);
    ul.b2[0] = __nv_bfloat162(l0, l1); ul.b2[1] = __nv_bfloat162(l2, l3);
    *(uint2*)(g_Ahi + (size_t)r * D_FEAT + lane * 4) = uh.u;
    *(uint2*)(g_Alo + (size_t)r * D_FEAT + lane * 4) = ul.u;
}

__global__ void split_W_kernel(const float* __restrict__ W) {
    int k = blockIdx.x;        // 0..127
    int n = threadIdx.x;       // 0..255
    float x = W[(size_t)k * UNITS + n];
    __nv_bfloat16 hi, lo;
    bf16_split(x, hi, lo);
    g_Whi[(size_t)n * D_FEAT + k] = hi;    // transposed [n][k]
    g_Wlo[(size_t)n * D_FEAT + k] = lo;
}

// ----------------------------------------------- mma.sync bf16x3 GEMM -------
// Term order (Ahi*Whi, Ahi*Wlo, Alo*Whi): A tile reloaded only at p=2.
// Fragments via ldmatrix.m8n8.x4 (conflict-free with 136-elem stride).
#define AS_STRIDE 136

__device__ __forceinline__ void ldmat_x4(uint32_t& r0, uint32_t& r1,
                                         uint32_t& r2, uint32_t& r3,
                                         uint32_t addr) {
    asm volatile("ldmatrix.sync.aligned.m8n8.x4.shared.b16 {%0,%1,%2,%3}, [%4];"
                 : "=r"(r0), "=r"(r1), "=r"(r2), "=r"(r3) : "r"(addr));
}

__global__ void __launch_bounds__(256)
gemm_mma_kernel(float* __restrict__ out) {
    extern __shared__ __nv_bfloat16 smem[];
    __nv_bfloat16* As = smem;                        // [128][AS_STRIDE]
    __nv_bfloat16* Bs = smem + 128 * AS_STRIDE;      // [128][AS_STRIDE], [n][k]

    uint32_t sbase;
    asm("{ .reg .u64 t; cvta.to.shared.u64 t, %1; cvt.u32.u64 %0, t; }"
        : "=r"(sbase) : "l"(smem));
    const uint32_t bs_base = sbase + 128 * AS_STRIDE * 2;

    const int tid  = threadIdx.x;
    const int wid  = tid >> 5;
    const int lane = tid & 31;
    const int g    = lane >> 2;
    const int tg   = lane & 3;
    const int wm   = (wid & 3) * 32;
    const int wn   = (wid >> 2) * 64;
    const int bm   = blockIdx.x * 128;
    const int bn   = blockIdx.y * 128;

    // per-thread ldmatrix base offsets (bytes), kk added per step
    uint32_t aoff[2];
    #pragma unroll
    for (int i = 0; i < 2; i++)
        aoff[i] = sbase +
            (uint32_t)(((wm + i * 16 + (lane & 15)) * AS_STRIDE +
                        (lane >> 4) * 8) * 2);
    uint32_t boff[4];
    #pragma unroll
    for (int jp = 0; jp < 4; jp++)
        boff[jp] = bs_base +
            (uint32_t)(((wn + jp * 16 + ((lane >> 4) * 8) + (lane & 7)) * AS_STRIDE +
                        ((lane >> 3) & 1) * 8) * 2);

    float acc[2][8][4];
    #pragma unroll
    for (int i = 0; i < 2; i++)
        #pragma unroll
        for (int j = 0; j < 8; j++)
            #pragma unroll
            for (int q = 0; q < 4; q++) acc[i][j][q] = 0.0f;

    const __nv_bfloat16* Asrc[3] = { g_Ahi, g_Ahi, g_Alo };
    const __nv_bfloat16* Bsrc[3] = { g_Whi, g_Wlo, g_Whi };

    for (int p = 0; p < 3; p++) {
        if (p != 1) {        // A tile unchanged between p=0 and p=1
            const uint4* Ag = (const uint4*)(Asrc[p] + (size_t)bm * D_FEAT);
            #pragma unroll
            for (int i = tid; i < 2048; i += 256) {
                int r = i >> 4, c = i & 15;
                *(uint4*)(As + r * AS_STRIDE + c * 8) = __ldg(Ag + i);
            }
        }
        const uint4* Bg = (const uint4*)(Bsrc[p] + (size_t)bn * D_FEAT);
        #pragma unroll
        for (int i = tid; i < 2048; i += 256) {
            int r = i >> 4, c = i & 15;
            *(uint4*)(Bs + r * AS_STRIDE + c * 8) = __ldg(Bg + i);
        }
        __syncthreads();

        #pragma unroll
        for (int kk = 0; kk < D_FEAT; kk += 16) {
            uint32_t a[2][4];
            #pragma unroll
            for (int i = 0; i < 2; i++)
                ldmat_x4(a[i][0], a[i][1], a[i][2], a[i][3],
                         aoff[i] + kk * 2);
            uint32_t b[8][2];
            #pragma unroll
            for (int jp = 0; jp < 4; jp++)
                ldmat_x4(b[jp * 2][0], b[jp * 2][1],
                         b[jp * 2 + 1][0], b[jp * 2 + 1][1],
                         boff[jp] + kk * 2);
            #pragma unroll
            for (int i = 0; i < 2; i++)
                #pragma unroll
                for (int j = 0; j < 8; j++) {
                    asm volatile(
                        "mma.sync.aligned.m16n8k16.row.col.f32.bf16.bf16.f32 "
                        "{%0,%1,%2,%3}, {%4,%5,%6,%7}, {%8,%9}, {%0,%1,%2,%3};"
                        : "+f"(acc[i][j][0]), "+f"(acc[i][j][1]),
                          "+f"(acc[i][j][2]), "+f"(acc[i][j][3])
                        : "r"(a[i][0]), "r"(a[i][1]), "r"(a[i][2]), "r"(a[i][3]),
                          "r"(b[j][0]), "r"(b[j][1]));
                }
        }
        __syncthreads();
    }

    #pragma unroll
    for (int i = 0; i < 2; i++) {
        int row0 = bm + wm + i * 16 + g;
        int row1 = row0 + 8;
        #pragma unroll
        for (int j = 0; j < 8; j++) {
            int col = bn + wn + j * 8 + tg * 2;
            if (row0 < N_NODES) {
                float2 o0 = make_float2(fmaxf(acc[i][j][0], 0.0f),
                                        fmaxf(acc[i][j][1], 0.0f));
                *(float2*)&out[(size_t)row0 * UNITS + col] = o0;
            }
            if (row1 < N_NODES) {
                float2 o1 = make_float2(fmaxf(acc[i][j][2], 0.0f),
                                        fmaxf(acc[i][j][3], 0.0f));
                *(float2*)&out[(size_t)row1 * UNITS + col] = o1;
            }
        }
    }
}

#define GEMM_SMEM_BYTES (2 * 128 * AS_STRIDE * 2)   // 69632

// ------------------------------------------------------------------ launch --
extern "C" void kernel_launch(void* const* d_in, const int* in_sizes, int n_in,
                              void* d_out, int out_size) {
    const float* features = (const float*)d_in[0];
    const int*   edge_row = (const int*)d_in[1];
    const int*   edge_col = (const int*)d_in[2];
    const float* edge_val = (const float*)d_in[3];
    const float* W        = (const float*)d_in[4];
    float*       out      = (float*)d_out;

    zero_kernel<<<(N_NODES + 255) / 256, 256>>>();
    fill_ell_kernel<<<(N_EDGES + 255) / 256, 256>>>(edge_row, edge_col, edge_val);

    const int nf4 = N_NODES * (D_FEAT / 4);
    normalize_kernel<<<(nf4 + 255) / 256, 256>>>(features);

    gather_kernel<<<(N_NODES * 32 + 255) / 256, 256>>>(features);

    split_W_kernel<<<D_FEAT, UNITS>>>(W);

    static bool smem_set = false;
    if (!smem_set) {
        cudaFuncSetAttribute(gemm_mma_kernel,
                             cudaFuncAttributeMaxDynamicSharedMemorySize,
                             GEMM_SMEM_BYTES);
        smem_set = true;
    }
    dim3 grid(N_PAD / 128, UNITS / 128);
    gemm_mma_kernel<<<grid, 256, GEMM_SMEM_BYTES>>>(out);
}

// round 8
// speedup vs baseline: 2.6168x; 1.3265x over previous
#include <cuda_runtime.h>
#include <cuda_fp16.h>
#include <cstdint>

#define N_NODES 50000
#define N_PAD   50048      // 391 * 128
#define N_EDGES 800000
#define D_FEAT  128
#define UNITS   256
#define ELLW    80         // padded ELL width (max degree ~35 whp)

// ---------------------------------------------------------------- scratch ---
__device__ unsigned long long g_pack[N_NODES];  // count<<42 | fix24(val sum)
__device__ int2   g_ell[(size_t)N_NODES * ELLW];   // {col, val-bits}
__device__ __half g_normh[(size_t)N_NODES * D_FEAT];
// fp16 GEMM operands (zero-init; pad rows never written -> stay zero)
__device__ __half g_Ah[(size_t)N_PAD * D_FEAT];
__device__ __half g_Wh[(size_t)UNITS * D_FEAT];    // transposed: [n][k]

// -------------------------------------------------------------------- zero --
__global__ void zero_kernel() {
    int i = blockIdx.x * blockDim.x + threadIdx.x;
    if (i < N_NODES) g_pack[i] = 0ull;
}

// ---------------------------------------- fused degree + count + ELL fill ---
__global__ void fill_ell_kernel(const int* __restrict__ erow,
                                const int* __restrict__ ecol,
                                const float* __restrict__ eval) {
    int e = blockIdx.x * blockDim.x + threadIdx.x;
    if (e >= N_EDGES) return;
    int   r = erow[e];
    float v = eval[e];
    unsigned long long q =
        (1ull << 42) + (unsigned long long)(v * 16777216.0f);
    unsigned long long old = atomicAdd(&g_pack[r], q);
    int slot = (int)(old >> 42);
    g_ell[(size_t)r * ELLW + slot] = make_int2(ecol[e], __float_as_int(v));
}

__device__ __forceinline__ float pack_to_inv(unsigned long long p) {
    float deg = (float)(p & ((1ull << 42) - 1)) * (1.0f / 16777216.0f);
    return rsqrtf(deg + 1.0f);
}

// ---------------------------------------------- normalize -> fp16 -----------
__global__ void normalize_kernel(const float* __restrict__ feat) {
    int idx = blockIdx.x * blockDim.x + threadIdx.x;   // 4-elem index
    const int total = N_NODES * (D_FEAT / 4);
    if (idx >= total) return;
    int n = idx >> 5;
    float inv = pack_to_inv(g_pack[n]);
    float4 f = __ldg(((const float4*)feat) + idx);
    __half2 a = __floats2half2_rn(f.x * inv, f.y * inv);
    __half2 b = __floats2half2_rn(f.z * inv, f.w * inv);
    union { __half2 h[2]; uint2 u; } u;
    u.h[0] = a; u.h[1] = b;
    ((uint2*)g_normh)[idx] = u.u;
}

// --------------------------------------------- gather SpMM (fp16 A out) -----
__global__ void __launch_bounds__(256)
gather_kernel(const float* __restrict__ feat) {
    int warp = (blockIdx.x * blockDim.x + threadIdx.x) >> 5;
    int lane = threadIdx.x & 31;
    if (warp >= N_NODES) return;
    const int r = warp;

    unsigned long long p = g_pack[r];
    const int deg = (int)(p >> 42);
    float inv  = pack_to_inv(p);
    float inv2 = inv * inv;
    float4 sf = __ldg((const float4*)(feat + (size_t)r * D_FEAT) + lane);
    float4 acc = make_float4(inv2 * sf.x, inv2 * sf.y, inv2 * sf.z, inv2 * sf.w);

    const int2* ebase = g_ell + (size_t)r * ELLW;

    int done = 0;
    while (done < deg) {
        const int chunk = min(32, deg - done);
        int2 ev = make_int2(0, 0);
        if (lane < chunk) ev = __ldg(ebase + done + lane);

        int d = 0;
        for (; d + 8 <= chunk; d += 8) {
            int   cs[8];
            float vs[8];
            #pragma unroll
            for (int j = 0; j < 8; j++) {
                cs[j] = __shfl_sync(0xffffffffu, ev.x, d + j);
                vs[j] = __uint_as_float(__shfl_sync(0xffffffffu, ev.y, d + j));
            }
            uint2 ms[8];
            #pragma unroll
            for (int j = 0; j < 8; j++)
                ms[j] = __ldg((const uint2*)(g_normh + (size_t)cs[j] * D_FEAT) + lane);
            #pragma unroll
            for (int j = 0; j < 8; j++) {
                union { uint2 u; __half2 h[2]; } m; m.u = ms[j];
                float2 f01 = __half22float2(m.h[0]);
                float2 f23 = __half22float2(m.h[1]);
                acc.x = fmaf(vs[j], f01.x, acc.x);
                acc.y = fmaf(vs[j], f01.y, acc.y);
                acc.z = fmaf(vs[j], f23.x, acc.z);
                acc.w = fmaf(vs[j], f23.y, acc.w);
            }
        }
        for (; d < chunk; d++) {
            int   c = __shfl_sync(0xffffffffu, ev.x, d);
            float v = __uint_as_float(__shfl_sync(0xffffffffu, ev.y, d));
            union { uint2 u; __half2 h[2]; } m;
            m.u = __ldg((const uint2*)(g_normh + (size_t)c * D_FEAT) + lane);
            float2 f01 = __half22float2(m.h[0]);
            float2 f23 = __half22float2(m.h[1]);
            acc.x = fmaf(v, f01.x, acc.x);
            acc.y = fmaf(v, f01.y, acc.y);
            acc.z = fmaf(v, f23.x, acc.z);
            acc.w = fmaf(v, f23.y, acc.w);
        }
        done += chunk;
    }

    // write fp16 A row directly
    union { __half2 h[2]; uint2 u; } o;
    o.h[0] = __floats2half2_rn(acc.x, acc.y);
    o.h[1] = __floats2half2_rn(acc.z, acc.w);
    *(uint2*)(g_Ah + (size_t)r * D_FEAT + lane * 4) = o.u;
}

// ------------------------------------------- W -> fp16 transposed -----------
__global__ void convert_W_kernel(const float* __restrict__ W) {
    int k = blockIdx.x;        // 0..127
    int n = threadIdx.x;       // 0..255
    g_Wh[(size_t)n * D_FEAT + k] = __float2half_rn(W[(size_t)k * UNITS + n]);
}

// --------------------------------------------- mma.sync fp16 GEMM -----------
// out[N,256] = relu( A(128-tile rows x 128 fp16) @ Wh^T ), single pass.
#define AS_STRIDE 136

__device__ __forceinline__ void ldmat_x4(uint32_t& r0, uint32_t& r1,
                                         uint32_t& r2, uint32_t& r3,
                                         uint32_t addr) {
    asm volatile("ldmatrix.sync.aligned.m8n8.x4.shared.b16 {%0,%1,%2,%3}, [%4];"
                 : "=r"(r0), "=r"(r1), "=r"(r2), "=r"(r3) : "r"(addr));
}

__global__ void __launch_bounds__(256)
gemm_mma_kernel(float* __restrict__ out) {
    extern __shared__ __half smem[];
    __half* As = smem;                        // [128][AS_STRIDE]
    __half* Bs = smem + 128 * AS_STRIDE;      // [128][AS_STRIDE], [n][k]

    uint32_t sbase;
    asm("{ .reg .u64 t; cvta.to.shared.u64 t, %1; cvt.u32.u64 %0, t; }"
        : "=r"(sbase) : "l"(smem));
    const uint32_t bs_base = sbase + 128 * AS_STRIDE * 2;

    const int tid  = threadIdx.x;
    const int wid  = tid >> 5;
    const int lane = tid & 31;
    const int g    = lane >> 2;
    const int tg   = lane & 3;
    const int wm   = (wid & 3) * 32;
    const int wn   = (wid >> 2) * 64;
    const int bm   = blockIdx.x * 128;
    const int bn   = blockIdx.y * 128;

    uint32_t aoff[2];
    #pragma unroll
    for (int i = 0; i < 2; i++)
        aoff[i] = sbase +
            (uint32_t)(((wm + i * 16 + (lane & 15)) * AS_STRIDE +
                        (lane >> 4) * 8) * 2);
    uint32_t boff[4];
    #pragma unroll
    for (int jp = 0; jp < 4; jp++)
        boff[jp] = bs_base +
            (uint32_t)(((wn + jp * 16 + ((lane >> 4) * 8) + (lane & 7)) * AS_STRIDE +
                        ((lane >> 3) & 1) * 8) * 2);

    float acc[2][8][4];
    #pragma unroll
    for (int i = 0; i < 2; i++)
        #pragma unroll
        for (int j = 0; j < 8; j++)
            #pragma unroll
            for (int q = 0; q < 4; q++) acc[i][j][q] = 0.0f;

    // fill tiles (A and B rows are contiguous: row length == K == 128)
    {
        const uint4* Ag = (const uint4*)(g_Ah + (size_t)bm * D_FEAT);
        const uint4* Bg = (const uint4*)(g_Wh + (size_t)bn * D_FEAT);
        #pragma unroll
        for (int i = tid; i < 2048; i += 256) {
            int r = i >> 4, c = i & 15;
            *(uint4*)(As + r * AS_STRIDE + c * 8) = __ldg(Ag + i);
        }
        #pragma unroll
        for (int i = tid; i < 2048; i += 256) {
            int r = i >> 4, c = i & 15;
            *(uint4*)(Bs + r * AS_STRIDE + c * 8) = __ldg(Bg + i);
        }
    }
    __syncthreads();

    #pragma unroll
    for (int kk = 0; kk < D_FEAT; kk += 16) {
        uint32_t a[2][4];
        #pragma unroll
        for (int i = 0; i < 2; i++)
            ldmat_x4(a[i][0], a[i][1], a[i][2], a[i][3], aoff[i] + kk * 2);
        uint32_t b[8][2];
        #pragma unroll
        for (int jp = 0; jp < 4; jp++)
            ldmat_x4(b[jp * 2][0], b[jp * 2][1],
                     b[jp * 2 + 1][0], b[jp * 2 + 1][1],
                     boff[jp] + kk * 2);
        #pragma unroll
        for (int i = 0; i < 2; i++)
            #pragma unroll
            for (int j = 0; j < 8; j++) {
                asm volatile(
                    "mma.sync.aligned.m16n8k16.row.col.f32.f16.f16.f32 "
                    "{%0,%1,%2,%3}, {%4,%5,%6,%7}, {%8,%9}, {%0,%1,%2,%3};"
                    : "+f"(acc[i][j][0]), "+f"(acc[i][j][1]),
                      "+f"(acc[i][j][2]), "+f"(acc[i][j][3])
                    : "r"(a[i][0]), "r"(a[i][1]), "r"(a[i][2]), "r"(a[i][3]),
                      "r"(b[j][0]), "r"(b[j][1]));
            }
    }

    #pragma unroll
    for (int i = 0; i < 2; i++) {
        int row0 = bm + wm + i * 16 + g;
        int row1 = row0 + 8;
        #pragma unroll
        for (int j = 0; j < 8; j++) {
            int col = bn + wn + j * 8 + tg * 2;
            if (row0 < N_NODES) {
                float2 o0 = make_float2(fmaxf(acc[i][j][0], 0.0f),
                                        fmaxf(acc[i][j][1], 0.0f));
                *(float2*)&out[(size_t)row0 * UNITS + col] = o0;
            }
            if (row1 < N_NODES) {
                float2 o1 = make_float2(fmaxf(acc[i][j][2], 0.0f),
                                        fmaxf(acc[i][j][3], 0.0f));
                *(float2*)&out[(size_t)row1 * UNITS + col] = o1;
            }
        }
    }
}

#define GEMM_SMEM_BYTES (2 * 128 * AS_STRIDE * 2)   // 69632

// ------------------------------------------------------------------ launch --
extern "C" void kernel_launch(void* const* d_in, const int* in_sizes, int n_in,
                              void* d_out, int out_size) {
    const float* features = (const float*)d_in[0];
    const int*   edge_row = (const int*)d_in[1];
    const int*   edge_col = (const int*)d_in[2];
    const float* edge_val = (const float*)d_in[3];
    const float* W        = (const float*)d_in[4];
    float*       out      = (float*)d_out;

    zero_kernel<<<(N_NODES + 255) / 256, 256>>>();
    fill_ell_kernel<<<(N_EDGES + 255) / 256, 256>>>(edge_row, edge_col, edge_val);

    const int nf4 = N_NODES * (D_FEAT / 4);
    normalize_kernel<<<(nf4 + 255) / 256, 256>>>(features);

    gather_kernel<<<(N_NODES * 32 + 255) / 256, 256>>>(features);

    convert_W_kernel<<<D_FEAT, UNITS>>>(W);

    static bool smem_set = false;
    if (!smem_set) {
        cudaFuncSetAttribute(gemm_mma_kernel,
                             cudaFuncAttributeMaxDynamicSharedMemorySize,
                             GEMM_SMEM_BYTES);
        smem_set = true;
    }
    dim3 grid(N_PAD / 128, UNITS / 128);
    gemm_mma_kernel<<<grid, 256, GEMM_SMEM_BYTES>>>(out);
}